// round 1
// baseline (speedup 1.0000x reference)
#include <cuda_runtime.h>

// ---------------- compile-time shapes ----------------
static constexpr int B_ = 2;
static constexpr int D0 = 41, H0 = 512, W0 = 512;
static constexpr int D1 = 21, H1 = 256, W1 = 256;
static constexpr int D2 = 11, H2 = 128, W2 = 128;
static constexpr int D3 = 5,  H3 = 64,  W3 = 64;
static constexpr int D4 = 2,  H4 = 64,  W4 = 64;

static constexpr int N0 = B_ * D0 * H0 * W0;   // 21,495,808
static constexpr int N1 = B_ * D1 * H1 * W1;   // 2,752,512
static constexpr int N2 = B_ * D2 * H2 * W2;   // 360,448
static constexpr int N3 = B_ * D3 * H3 * W3;   // 40,960
static constexpr int N4 = B_ * D4 * H4 * W4;   // 16,384

// ---------------- scratch (device globals; no runtime alloc) ----------------
__device__ __align__(16) float4        g_dense0[N0];          // {f0,f1,f2,mask}
__device__ __align__(16) float         g_h1[(size_t)N1 * 16];
__device__ unsigned char               g_m1[N1];
__device__ __align__(16) float         g_h2[(size_t)N2 * 32];
__device__ unsigned char               g_m2[N2];
__device__ __align__(16) float         g_h3[(size_t)N3 * 64];
__device__ unsigned char               g_m3[N3];

// ---------------- helpers ----------------
template<int CO>
__device__ __forceinline__ void fma_ci4(float (&acc)[CO], float4 v, const float* wt) {
    float vv[4] = {v.x, v.y, v.z, v.w};
#pragma unroll
    for (int u = 0; u < 4; u++) {
        const float4* wp = reinterpret_cast<const float4*>(wt + u * CO);
#pragma unroll
        for (int j = 0; j < CO / 4; j++) {
            float4 ww = wp[j];
            acc[j*4+0] = fmaf(vv[u], ww.x, acc[j*4+0]);
            acc[j*4+1] = fmaf(vv[u], ww.y, acc[j*4+1]);
            acc[j*4+2] = fmaf(vv[u], ww.z, acc[j*4+2]);
            acc[j*4+3] = fmaf(vv[u], ww.w, acc[j*4+3]);
        }
    }
}

// accumulate one tap: acc[co] += sum_ci hin[ci] * wt[ci*CO + co]
template<int CI, int CO>
__device__ __forceinline__ void conv_tap(float (&acc)[CO], const float* __restrict__ hin,
                                         const float* __restrict__ wt) {
#pragma unroll
    for (int c4 = 0; c4 < CI / 4; c4++) {
        float4 v = reinterpret_cast<const float4*>(hin)[c4];
        fma_ci4<CO>(acc, v, wt + c4 * 4 * CO);
    }
}

template<int CO>
__device__ __forceinline__ void bn_relu_store(float* __restrict__ outp, const float (&acc)[CO],
                                              const float* ssc, const float* ssh, float m) {
#pragma unroll
    for (int j = 0; j < CO / 4; j++) {
        float4 o;
        o.x = fmaxf(fmaf(acc[j*4+0], ssc[j*4+0], ssh[j*4+0]), 0.f) * m;
        o.y = fmaxf(fmaf(acc[j*4+1], ssc[j*4+1], ssh[j*4+1]), 0.f) * m;
        o.z = fmaxf(fmaf(acc[j*4+2], ssc[j*4+2], ssh[j*4+2]), 0.f) * m;
        o.w = fmaxf(fmaf(acc[j*4+3], ssc[j*4+3], ssh[j*4+3]), 0.f) * m;
        reinterpret_cast<float4*>(outp)[j] = o;
    }
}

__device__ __forceinline__ void load_bn(int co_base, int nco, int tid,
                                        const float* g, const float* bb,
                                        const float* rm, const float* rv,
                                        float* ssc, float* ssh) {
    if (tid < nco) {
        int co = co_base + tid;
        float sc = g[co] * rsqrtf(rv[co] + 1e-3f);
        ssc[tid] = sc;
        ssh[tid] = bb[co] - rm[co] * sc;
    }
}

// ---------------- kernels ----------------
__global__ void k_zero() {
    int i = blockIdx.x * blockDim.x + threadIdx.x;
    if (i < N0) g_dense0[i] = make_float4(0.f, 0.f, 0.f, 0.f);
}

__global__ void k_scatter(const float* __restrict__ f, const int* __restrict__ c, int nv) {
    int i = blockIdx.x * blockDim.x + threadIdx.x;
    if (i >= nv) return;
    int b = c[4*i], z = c[4*i+1], y = c[4*i+2], x = c[4*i+3];
    float* p = reinterpret_cast<float*>(&g_dense0[(((size_t)b * D0 + z) * H0 + y) * W0 + x]);
    atomicAdd(p + 0, f[3*i + 0]);
    atomicAdd(p + 1, f[3*i + 1]);
    atomicAdd(p + 2, f[3*i + 2]);
    p[3] = 1.0f;  // benign same-value race
}

// conv1: 3 -> 16, k=3, s=2, pad=1; input dense0 (float4 w/ mask), output h1/m1
__global__ void __launch_bounds__(128) k_conv1(const float* __restrict__ w,
                                               const float* __restrict__ g,
                                               const float* __restrict__ bb,
                                               const float* __restrict__ rm,
                                               const float* __restrict__ rv) {
    __shared__ __align__(16) float wsh[27 * 3 * 16];  // [tap][ci][co]
    __shared__ float ssc[16], ssh[16];
    for (int i = threadIdx.x; i < 27 * 3 * 16; i += blockDim.x) {
        int co = i & 15, ci = (i >> 4) % 3, tap = i / 48;
        wsh[i] = w[(co * 3 + ci) * 27 + tap];
    }
    load_bn(0, 16, threadIdx.x, g, bb, rm, rv, ssc, ssh);
    __syncthreads();

    int idx = blockIdx.x * blockDim.x + threadIdx.x;
    if (idx >= N1) return;
    int ow = idx % W1; int t = idx / W1;
    int oh = t % H1; t /= H1;
    int od = t % D1; int b = t / D1;

    float acc[16];
#pragma unroll
    for (int i = 0; i < 16; i++) acc[i] = 0.f;
    float msum = 0.f;

#pragma unroll
    for (int kd = 0; kd < 3; kd++) {
        int id = 2 * od - 1 + kd;
        if ((unsigned)id >= (unsigned)D0) continue;
#pragma unroll
        for (int kh = 0; kh < 3; kh++) {
            int ih = 2 * oh - 1 + kh;
            if ((unsigned)ih >= (unsigned)H0) continue;
#pragma unroll
            for (int kw = 0; kw < 3; kw++) {
                int iw = 2 * ow - 1 + kw;
                if ((unsigned)iw >= (unsigned)W0) continue;
                float4 v = g_dense0[(((size_t)b * D0 + id) * H0 + ih) * W0 + iw];
                msum += v.w;
                if (v.w != 0.f) {
                    int tap = (kd * 3 + kh) * 3 + kw;
                    const float4* wp = reinterpret_cast<const float4*>(&wsh[tap * 48]);
                    float vv[3] = {v.x, v.y, v.z};
#pragma unroll
                    for (int ci = 0; ci < 3; ci++) {
#pragma unroll
                        for (int j = 0; j < 4; j++) {
                            float4 ww = wp[ci * 4 + j];
                            acc[j*4+0] = fmaf(vv[ci], ww.x, acc[j*4+0]);
                            acc[j*4+1] = fmaf(vv[ci], ww.y, acc[j*4+1]);
                            acc[j*4+2] = fmaf(vv[ci], ww.z, acc[j*4+2]);
                            acc[j*4+3] = fmaf(vv[ci], ww.w, acc[j*4+3]);
                        }
                    }
                }
            }
        }
    }
    float m = (msum > 0.f) ? 1.f : 0.f;
    bn_relu_store<16>(&g_h1[(size_t)idx * 16], acc, ssc, ssh, m);
    g_m1[idx] = (msum > 0.f) ? 1 : 0;
}

// conv2: 16 -> 32, k=3, s=2, pad=1; per-kd weight staging in shared
__global__ void __launch_bounds__(128) k_conv2(const float* __restrict__ w,
                                               const float* __restrict__ g,
                                               const float* __restrict__ bb,
                                               const float* __restrict__ rm,
                                               const float* __restrict__ rv) {
    __shared__ __align__(16) float wsh[9 * 16 * 32];  // one kd slice: [tap9][ci][co]
    __shared__ float ssc[32], ssh[32];
    load_bn(0, 32, threadIdx.x, g, bb, rm, rv, ssc, ssh);

    int idx = blockIdx.x * blockDim.x + threadIdx.x;
    bool valid = idx < N2;
    int lin = valid ? idx : 0;
    int ow = lin % W2; int t = lin / W2;
    int oh = t % H2; t /= H2;
    int od = t % D2; int b = t / D2;

    float acc[32];
#pragma unroll
    for (int i = 0; i < 32; i++) acc[i] = 0.f;
    int mc = 0;

    for (int kd = 0; kd < 3; kd++) {
        __syncthreads();
        for (int i = threadIdx.x; i < 9 * 16 * 32; i += blockDim.x) {
            int co = i & 31, ci = (i >> 5) & 15, tap9 = i >> 9;
            wsh[i] = w[(co * 16 + ci) * 27 + kd * 9 + tap9];
        }
        __syncthreads();
        if (!valid) continue;
        int id = 2 * od - 1 + kd;
        if ((unsigned)id >= (unsigned)D1) continue;
#pragma unroll
        for (int kh = 0; kh < 3; kh++) {
            int ih = 2 * oh - 1 + kh;
            if ((unsigned)ih >= (unsigned)H1) continue;
#pragma unroll
            for (int kw = 0; kw < 3; kw++) {
                int iw = 2 * ow - 1 + kw;
                if ((unsigned)iw >= (unsigned)W1) continue;
                size_t cin = (((size_t)b * D1 + id) * H1 + ih) * W1 + iw;
                unsigned char mv = g_m1[cin];
                mc += mv;
                if (mv) {
                    int tap9 = kh * 3 + kw;
                    conv_tap<16, 32>(acc, &g_h1[cin * 16], &wsh[tap9 * 16 * 32]);
                }
            }
        }
    }
    if (!valid) return;
    float m = (mc > 0) ? 1.f : 0.f;
    bn_relu_store<32>(&g_h2[(size_t)lin * 32], acc, ssc, ssh, m);
    g_m2[lin] = (mc > 0) ? 1 : 0;
}

// conv3: 32 -> 64, k=3, s=2, pad D=0 / HW=1; co split across blockIdx.y, per-kd staging
__global__ void __launch_bounds__(128) k_conv3(const float* __restrict__ w,
                                               const float* __restrict__ g,
                                               const float* __restrict__ bb,
                                               const float* __restrict__ rm,
                                               const float* __restrict__ rv) {
    __shared__ __align__(16) float wsh[9 * 32 * 32];  // one kd slice, half of co
    __shared__ float ssc[32], ssh[32];
    int coBase = blockIdx.y * 32;
    load_bn(coBase, 32, threadIdx.x, g, bb, rm, rv, ssc, ssh);

    int idx = blockIdx.x * blockDim.x + threadIdx.x;
    bool valid = idx < N3;
    int lin = valid ? idx : 0;
    int ow = lin % W3; int t = lin / W3;
    int oh = t % H3; t /= H3;
    int od = t % D3; int b = t / D3;

    float acc[32];
#pragma unroll
    for (int i = 0; i < 32; i++) acc[i] = 0.f;
    int mc = 0;

    for (int kd = 0; kd < 3; kd++) {
        __syncthreads();
        for (int i = threadIdx.x; i < 9 * 32 * 32; i += blockDim.x) {
            int co = i & 31, ci = (i >> 5) & 31, tap9 = i >> 10;
            wsh[i] = w[((coBase + co) * 32 + ci) * 27 + kd * 9 + tap9];
        }
        __syncthreads();
        if (!valid) continue;
        int id = 2 * od + kd;  // pad 0, always in range [0, 10]
#pragma unroll
        for (int kh = 0; kh < 3; kh++) {
            int ih = 2 * oh - 1 + kh;
            if ((unsigned)ih >= (unsigned)H2) continue;
#pragma unroll
            for (int kw = 0; kw < 3; kw++) {
                int iw = 2 * ow - 1 + kw;
                if ((unsigned)iw >= (unsigned)W2) continue;
                size_t cin = (((size_t)b * D2 + id) * H2 + ih) * W2 + iw;
                unsigned char mv = g_m2[cin];
                mc += mv;
                if (mv) {
                    int tap9 = kh * 3 + kw;
                    conv_tap<32, 32>(acc, &g_h2[cin * 32], &wsh[tap9 * 32 * 32]);
                }
            }
        }
    }
    if (!valid) return;
    float m = (mc > 0) ? 1.f : 0.f;
    bn_relu_store<32>(&g_h3[(size_t)lin * 64 + coBase], acc, ssc, ssh, m);
    if (coBase == 0) g_m3[lin] = (mc > 0) ? 1 : 0;
}

// conv4: 64 -> 64, k=(3,1,1), s=(2,1,1), pad 0; writes final output with reshape
__global__ void __launch_bounds__(128) k_conv4(const float* __restrict__ w,
                                               const float* __restrict__ g,
                                               const float* __restrict__ bb,
                                               const float* __restrict__ rm,
                                               const float* __restrict__ rv,
                                               float* __restrict__ out) {
    __shared__ __align__(16) float wsh[64 * 64];  // one kd slice: [ci][co]
    __shared__ float ssc[64], ssh[64];
    load_bn(0, 64, threadIdx.x, g, bb, rm, rv, ssc, ssh);

    int idx = blockIdx.x * blockDim.x + threadIdx.x;
    bool valid = idx < N4;
    int lin = valid ? idx : 0;
    int ow = lin % W4; int t = lin / W4;
    int oh = t % H4; t /= H4;
    int od = t % D4; int b = t / D4;

    float acc[64];
#pragma unroll
    for (int i = 0; i < 64; i++) acc[i] = 0.f;
    int mc = 0;

    for (int kd = 0; kd < 3; kd++) {
        __syncthreads();
        for (int i = threadIdx.x; i < 64 * 64; i += blockDim.x) {
            int co = i & 63, ci = i >> 6;
            wsh[i] = w[(co * 64 + ci) * 3 + kd];
        }
        __syncthreads();
        if (!valid) continue;
        int id = 2 * od + kd;  // always in [0, 4]
        size_t cin = (((size_t)b * D3 + id) * H3 + oh) * W3 + ow;
        unsigned char mv = g_m3[cin];
        mc += mv;
        if (mv) conv_tap<64, 64>(acc, &g_h3[cin * 64], wsh);
    }
    if (!valid) return;
    float m = (mc > 0) ? 1.f : 0.f;
    // out[b][co*2+od][oh][ow], shape (2, 128, 64, 64)
    size_t base = (size_t)b * 128 * 4096 + (size_t)oh * 64 + ow;
#pragma unroll
    for (int co = 0; co < 64; co++) {
        float o = fmaxf(fmaf(acc[co], ssc[co], ssh[co]), 0.f) * m;
        out[base + (size_t)(co * 2 + od) * 4096] = o;
    }
}

// ---------------- launch ----------------
extern "C" void kernel_launch(void* const* d_in, const int* in_sizes, int n_in,
                              void* d_out, int out_size) {
    const float* vf    = (const float*)d_in[0];
    const int*   coors = (const int*)d_in[1];
    int nv = in_sizes[0] / 3;

    const float* w1 = (const float*)d_in[3];
    const float* g1 = (const float*)d_in[4];
    const float* b1 = (const float*)d_in[5];
    const float* m1 = (const float*)d_in[6];
    const float* v1 = (const float*)d_in[7];
    const float* w2 = (const float*)d_in[8];
    const float* g2 = (const float*)d_in[9];
    const float* b2 = (const float*)d_in[10];
    const float* m2 = (const float*)d_in[11];
    const float* v2 = (const float*)d_in[12];
    const float* w3 = (const float*)d_in[13];
    const float* g3 = (const float*)d_in[14];
    const float* b3 = (const float*)d_in[15];
    const float* m3 = (const float*)d_in[16];
    const float* v3 = (const float*)d_in[17];
    const float* w4 = (const float*)d_in[18];
    const float* g4 = (const float*)d_in[19];
    const float* b4 = (const float*)d_in[20];
    const float* m4 = (const float*)d_in[21];
    const float* v4 = (const float*)d_in[22];

    k_zero<<<(N0 + 255) / 256, 256>>>();
    k_scatter<<<(nv + 255) / 256, 256>>>(vf, coors, nv);
    k_conv1<<<(N1 + 127) / 128, 128>>>(w1, g1, b1, m1, v1);
    k_conv2<<<(N2 + 127) / 128, 128>>>(w2, g2, b2, m2, v2);
    dim3 grid3((N3 + 127) / 128, 2);
    k_conv3<<<grid3, 128>>>(w3, g3, b3, m3, v3);
    k_conv4<<<(N4 + 127) / 128, 128>>>(w4, g4, b4, m4, v4, (float*)d_out);
}

// round 2
// speedup vs baseline: 1.5408x; 1.5408x over previous
#include <cuda_runtime.h>

// ---------------- compile-time shapes ----------------
static constexpr int B_ = 2;
static constexpr int D0 = 41, H0 = 512, W0 = 512;
static constexpr int D1 = 21, H1 = 256, W1 = 256;
static constexpr int D2 = 11, H2 = 128, W2 = 128;
static constexpr int D3 = 5,  H3 = 64,  W3 = 64;

static constexpr int N0 = B_ * D0 * H0 * W0;   // 21,495,808
static constexpr int N1 = B_ * D1 * H1 * W1;   // 2,752,512
static constexpr int N2 = B_ * D2 * H2 * W2;   // 360,448
static constexpr int N3 = B_ * D3 * H3 * W3;   // 40,960
static constexpr int N4 = B_ * 2 * H3 * W3;    // 16,384 output points (od in {0,1})
static constexpr int NW0 = N0 / 32;            // 671,744 bitmap words

// ---------------- scratch (device globals; no runtime alloc) ----------------
__device__ __align__(16) float4        g_dense0[N0];     // xyz features (w unused); only active cells valid
__device__ __align__(16) unsigned      g_bits[NW0];      // occupancy bitmap, 1 bit/cell
__device__ __align__(16) float         g_h1[(size_t)N1 * 16];
__device__ unsigned char               g_m1[N1];
__device__ __align__(16) float         g_h2[(size_t)N2 * 32];
__device__ unsigned char               g_m2[N2];
__device__ __align__(16) float         g_h3[(size_t)N3 * 64];
__device__ unsigned char               g_m3[N3];

// transposed weights + folded BN
__device__ __align__(16) float g_wt1[27 * 3 * 16];    // [tap][ci][co]
__device__ __align__(16) float g_wt2[27 * 4 * 32 * 4]; // [tap][g4][co32] float4-of-ci
__device__ __align__(16) float g_wt3[27 * 8 * 64 * 4]; // [tap][g8][co64] float4-of-ci
__device__ __align__(16) float g_wt4[3 * 16 * 64 * 4]; // [kd][g16][co64] float4-of-ci
__device__ float g_sc1[16], g_sh1[16];
__device__ float g_sc2[32], g_sh2[32];
__device__ float g_sc3[64], g_sh3[64];
__device__ float g_sc4[64], g_sh4[64];

// ---------------- prep: transpose weights, fold BN ----------------
__global__ void k_prep(const float* __restrict__ w1, const float* __restrict__ g1,
                       const float* __restrict__ b1, const float* __restrict__ rm1,
                       const float* __restrict__ rv1,
                       const float* __restrict__ w2, const float* __restrict__ g2,
                       const float* __restrict__ b2, const float* __restrict__ rm2,
                       const float* __restrict__ rv2,
                       const float* __restrict__ w3, const float* __restrict__ g3,
                       const float* __restrict__ b3, const float* __restrict__ rm3,
                       const float* __restrict__ rv3,
                       const float* __restrict__ w4, const float* __restrict__ g4,
                       const float* __restrict__ b4, const float* __restrict__ rm4,
                       const float* __restrict__ rv4) {
    int i = blockIdx.x * blockDim.x + threadIdx.x;
    if (i < 1296) {  // conv1 [tap][ci][co16]
        int co = i & 15, ci = (i >> 4) % 3, tap = i / 48;
        g_wt1[i] = w1[(co * 3 + ci) * 27 + tap];
    }
    if (i < 13824) { // conv2 [tap][g4][co32][e4], ci = 4g+e
        int e = i & 3, co = (i >> 2) & 31, gg = (i >> 7) & 3, tap = i >> 9;
        g_wt2[i] = w2[(co * 16 + (4 * gg + e)) * 27 + tap];
    }
    if (i < 55296) { // conv3 [tap][g8][co64][e4]
        int e = i & 3, co = (i >> 2) & 63, gg = (i >> 8) & 7, tap = i >> 11;
        g_wt3[i] = w3[(co * 32 + (4 * gg + e)) * 27 + tap];
    }
    if (i < 12288) { // conv4 [kd][g16][co64][e4]
        int e = i & 3, co = (i >> 2) & 63, gg = (i >> 8) & 15, kd = i >> 12;
        g_wt4[i] = w4[(co * 64 + (4 * gg + e)) * 3 + kd];
    }
    if (i < 16) { float s = g1[i] * rsqrtf(rv1[i] + 1e-3f); g_sc1[i] = s; g_sh1[i] = b1[i] - rm1[i] * s; }
    if (i < 32) { float s = g2[i] * rsqrtf(rv2[i] + 1e-3f); g_sc2[i] = s; g_sh2[i] = b2[i] - rm2[i] * s; }
    if (i < 64) {
        float s3 = g3[i] * rsqrtf(rv3[i] + 1e-3f); g_sc3[i] = s3; g_sh3[i] = b3[i] - rm3[i] * s3;
        float s4 = g4[i] * rsqrtf(rv4[i] + 1e-3f); g_sc4[i] = s4; g_sh4[i] = b4[i] - rm4[i] * s4;
    }
}

// ---------------- scatter ----------------
__global__ void k_zerobits() {
    int i = blockIdx.x * blockDim.x + threadIdx.x;
    if (i < NW0 / 4) reinterpret_cast<uint4*>(g_bits)[i] = make_uint4(0, 0, 0, 0);
}

__global__ void k_scatA(const int* __restrict__ c, int nv) {
    int i = blockIdx.x * blockDim.x + threadIdx.x;
    if (i >= nv) return;
    int b = c[4*i], z = c[4*i+1], y = c[4*i+2], x = c[4*i+3];
    size_t cell = (((size_t)b * D0 + z) * H0 + y) * W0 + x;
    g_dense0[cell] = make_float4(0.f, 0.f, 0.f, 0.f);   // benign race (same value)
    atomicOr(&g_bits[cell >> 5], 1u << (cell & 31));
}

__global__ void k_scatB(const float* __restrict__ f, const int* __restrict__ c, int nv) {
    int i = blockIdx.x * blockDim.x + threadIdx.x;
    if (i >= nv) return;
    int b = c[4*i], z = c[4*i+1], y = c[4*i+2], x = c[4*i+3];
    size_t cell = (((size_t)b * D0 + z) * H0 + y) * W0 + x;
    float* p = reinterpret_cast<float*>(&g_dense0[cell]);
    atomicAdd(p + 0, f[3*i + 0]);
    atomicAdd(p + 1, f[3*i + 1]);
    atomicAdd(p + 2, f[3*i + 2]);
}

// ---------------- conv1: 3->16, k3 s2 pad1, bitmap-gated, thread per point ----------------
__global__ void __launch_bounds__(128) k_conv1() {
    int idx = blockIdx.x * blockDim.x + threadIdx.x;   // grid exact: N1 % 128 == 0
    int lane = threadIdx.x & 31;
    int ow = idx & 255; int t = idx >> 8;
    int oh = t & 255; t >>= 8;
    int od = t % D1; int b = t / D1;
    int base = ow - lane;            // warp-uniform (W1=256 is 32-aligned)
    int wk = base >> 4;              // word index of cell 2*base within row

    // gather 27 bits: 9 rows x 3 words (warp-uniform loads), extract per-thread
    unsigned bits27 = 0;
#pragma unroll
    for (int kd = 0; kd < 3; kd++) {
        int id = 2 * od - 1 + kd;
        bool dok = (unsigned)id < (unsigned)D0;
#pragma unroll
        for (int kh = 0; kh < 3; kh++) {
            int ih = 2 * oh - 1 + kh;
            bool rok = dok && ((unsigned)ih < (unsigned)H0);
            unsigned A = 0, Bw = 0, Cw = 0;
            if (rok) {
                size_t rw = ((((size_t)b * D0 + id) * H0) + ih) * (W0 / 32);
                if (wk > 0) A = g_bits[rw + wk - 1];
                Bw = g_bits[rw + wk];
                if (wk < 15) Cw = g_bits[rw + wk + 1];
            }
#pragma unroll
            for (int kw = 0; kw < 3; kw++) {
                unsigned qq = 2 * lane + 31 + kw;     // offset in 96-bit window
                unsigned word = (qq < 32) ? A : ((qq < 64) ? Bw : Cw);
                unsigned bit = (word >> (qq & 31)) & 1u;
                bits27 |= bit << ((kd * 3 + kh) * 3 + kw);
            }
        }
    }
    if (!bits27) { g_m1[idx] = 0; return; }

    float acc[16];
#pragma unroll
    for (int i = 0; i < 16; i++) acc[i] = 0.f;
    unsigned bits = bits27;
    const float4* wt = reinterpret_cast<const float4*>(g_wt1);
    while (bits) {
        int tap = __ffs(bits) - 1; bits &= bits - 1;
        int kd = tap / 9, kh = (tap / 3) % 3, kw = tap % 3;
        int id = 2 * od - 1 + kd, ih = 2 * oh - 1 + kh, iw = 2 * ow - 1 + kw;
        size_t cell = (((size_t)b * D0 + id) * H0 + ih) * W0 + iw;
        float4 v = __ldg(&g_dense0[cell]);
        float vv[3] = {v.x, v.y, v.z};
#pragma unroll
        for (int ci = 0; ci < 3; ci++) {
#pragma unroll
            for (int j = 0; j < 4; j++) {
                float4 ww = __ldg(wt + (tap * 3 + ci) * 4 + j);
                acc[j*4+0] = fmaf(vv[ci], ww.x, acc[j*4+0]);
                acc[j*4+1] = fmaf(vv[ci], ww.y, acc[j*4+1]);
                acc[j*4+2] = fmaf(vv[ci], ww.z, acc[j*4+2]);
                acc[j*4+3] = fmaf(vv[ci], ww.w, acc[j*4+3]);
            }
        }
    }
    float* outp = &g_h1[(size_t)idx * 16];
#pragma unroll
    for (int j = 0; j < 4; j++) {
        float4 o;
        o.x = fmaxf(fmaf(acc[j*4+0], g_sc1[j*4+0], g_sh1[j*4+0]), 0.f);
        o.y = fmaxf(fmaf(acc[j*4+1], g_sc1[j*4+1], g_sh1[j*4+1]), 0.f);
        o.z = fmaxf(fmaf(acc[j*4+2], g_sc1[j*4+2], g_sh1[j*4+2]), 0.f);
        o.w = fmaxf(fmaf(acc[j*4+3], g_sc1[j*4+3], g_sh1[j*4+3]), 0.f);
        reinterpret_cast<float4*>(outp)[j] = o;
    }
    g_m1[idx] = 1;
}

// ---------------- conv2: 16->32, k3 s2 pad1; warp per point, lane = co ----------------
__global__ void __launch_bounds__(256) k_conv2() {
    int gw = (blockIdx.x * blockDim.x + threadIdx.x) >> 5;   // grid exact
    int lane = threadIdx.x & 31;
    int ow = gw & 127; int t = gw >> 7;
    int oh = t & 127; t >>= 7;
    int od = t % D2; int b = t / D2;

    unsigned on = 0;
    if (lane < 27) {
        int kd = lane / 9, kh = (lane / 3) % 3, kw = lane % 3;
        int id = 2*od - 1 + kd, ih = 2*oh - 1 + kh, iw = 2*ow - 1 + kw;
        if ((unsigned)id < (unsigned)D1 && (unsigned)ih < (unsigned)H1 && (unsigned)iw < (unsigned)W1) {
            size_t cin = (((size_t)b * D1 + id) * H1 + ih) * W1 + iw;
            on = g_m1[cin];
        }
    }
    unsigned bits = __ballot_sync(0xffffffffu, on != 0);
    if (!bits) { if (lane == 0) g_m2[gw] = 0; return; }

    float acc = 0.f;
    const float4* wtb = reinterpret_cast<const float4*>(g_wt2);
    while (bits) {
        int tap = __ffs(bits) - 1; bits &= bits - 1;
        int kd = tap / 9, kh = (tap / 3) % 3, kw = tap % 3;
        int id = 2*od - 1 + kd, ih = 2*oh - 1 + kh, iw = 2*ow - 1 + kw;
        size_t cin = (((size_t)b * D1 + id) * H1 + ih) * W1 + iw;
        const float4* hin = reinterpret_cast<const float4*>(&g_h1[cin * 16]);
        const float4* wv = wtb + tap * 128 + lane;
#pragma unroll
        for (int gg = 0; gg < 4; gg++) {
            float4 v  = __ldg(hin + gg);          // warp-uniform broadcast
            float4 ww = __ldg(wv + gg * 32);      // coalesced
            acc = fmaf(v.x, ww.x, acc);
            acc = fmaf(v.y, ww.y, acc);
            acc = fmaf(v.z, ww.z, acc);
            acc = fmaf(v.w, ww.w, acc);
        }
    }
    float o = fmaxf(fmaf(acc, g_sc2[lane], g_sh2[lane]), 0.f);
    g_h2[(size_t)gw * 32 + lane] = o;
    if (lane == 0) g_m2[gw] = 1;
}

// ---------------- conv3: 32->64, k3 s2 padD0/HW1; warp per point, lane -> {co, co+32} ----------------
__global__ void __launch_bounds__(256) k_conv3() {
    int gw = (blockIdx.x * blockDim.x + threadIdx.x) >> 5;   // grid exact
    int lane = threadIdx.x & 31;
    int ow = gw & 63; int t = gw >> 6;
    int oh = t & 63; t >>= 6;
    int od = t % D3; int b = t / D3;

    unsigned on = 0;
    if (lane < 27) {
        int kd = lane / 9, kh = (lane / 3) % 3, kw = lane % 3;
        int id = 2*od + kd;                       // always in [0, 10]
        int ih = 2*oh - 1 + kh, iw = 2*ow - 1 + kw;
        if ((unsigned)ih < (unsigned)H2 && (unsigned)iw < (unsigned)W2) {
            size_t cin = (((size_t)b * D2 + id) * H2 + ih) * W2 + iw;
            on = g_m2[cin];
        }
    }
    unsigned bits = __ballot_sync(0xffffffffu, on != 0);
    if (!bits) { if (lane == 0) g_m3[gw] = 0; return; }

    float acc0 = 0.f, acc1 = 0.f;
    const float4* wtb = reinterpret_cast<const float4*>(g_wt3);
    while (bits) {
        int tap = __ffs(bits) - 1; bits &= bits - 1;
        int kd = tap / 9, kh = (tap / 3) % 3, kw = tap % 3;
        int id = 2*od + kd, ih = 2*oh - 1 + kh, iw = 2*ow - 1 + kw;
        size_t cin = (((size_t)b * D2 + id) * H2 + ih) * W2 + iw;
        const float4* hin = reinterpret_cast<const float4*>(&g_h2[cin * 32]);
        const float4* wv = wtb + tap * 512 + lane;
#pragma unroll
        for (int gg = 0; gg < 8; gg++) {
            float4 v   = __ldg(hin + gg);
            float4 w0  = __ldg(wv + gg * 64);
            float4 w1  = __ldg(wv + gg * 64 + 32);
            acc0 = fmaf(v.x, w0.x, acc0); acc0 = fmaf(v.y, w0.y, acc0);
            acc0 = fmaf(v.z, w0.z, acc0); acc0 = fmaf(v.w, w0.w, acc0);
            acc1 = fmaf(v.x, w1.x, acc1); acc1 = fmaf(v.y, w1.y, acc1);
            acc1 = fmaf(v.z, w1.z, acc1); acc1 = fmaf(v.w, w1.w, acc1);
        }
    }
    float o0 = fmaxf(fmaf(acc0, g_sc3[lane],      g_sh3[lane]),      0.f);
    float o1 = fmaxf(fmaf(acc1, g_sc3[lane + 32], g_sh3[lane + 32]), 0.f);
    g_h3[(size_t)gw * 64 + lane]      = o0;
    g_h3[(size_t)gw * 64 + lane + 32] = o1;
    if (lane == 0) g_m3[gw] = 1;
}

// ---------------- conv4: 64->64, k(3,1,1) s(2,1,1) pad0; warp per point; writes d_out ----------------
__global__ void __launch_bounds__(256) k_conv4(float* __restrict__ out) {
    int gw = (blockIdx.x * blockDim.x + threadIdx.x) >> 5;   // grid exact
    int lane = threadIdx.x & 31;
    int ow = gw & 63; int t = gw >> 6;
    int oh = t & 63; t >>= 6;
    int od = t & 1; int b = t >> 1;

    unsigned on = 0;
    if (lane < 3) {
        int id = 2*od + lane;                    // in [0,4]
        size_t cin = (((size_t)b * D3 + id) * H3 + oh) * W3 + ow;
        on = g_m3[cin];
    }
    unsigned bits = __ballot_sync(0xffffffffu, on != 0);

    // out[b][co*2+od][oh][ow]; co0 = lane, co1 = lane+32
    size_t obase = (size_t)b * 128 * 4096 + (size_t)oh * 64 + ow;
    size_t oi0 = obase + (size_t)(lane * 2 + od) * 4096;
    size_t oi1 = obase + (size_t)((lane + 32) * 2 + od) * 4096;

    if (!bits) { out[oi0] = 0.f; out[oi1] = 0.f; return; }

    float acc0 = 0.f, acc1 = 0.f;
    const float4* wtb = reinterpret_cast<const float4*>(g_wt4);
    while (bits) {
        int kd = __ffs(bits) - 1; bits &= bits - 1;
        int id = 2*od + kd;
        size_t cin = (((size_t)b * D3 + id) * H3 + oh) * W3 + ow;
        const float4* hin = reinterpret_cast<const float4*>(&g_h3[cin * 64]);
        const float4* wv = wtb + kd * 1024 + lane;
#pragma unroll
        for (int gg = 0; gg < 16; gg++) {
            float4 v  = __ldg(hin + gg);
            float4 w0 = __ldg(wv + gg * 64);
            float4 w1 = __ldg(wv + gg * 64 + 32);
            acc0 = fmaf(v.x, w0.x, acc0); acc0 = fmaf(v.y, w0.y, acc0);
            acc0 = fmaf(v.z, w0.z, acc0); acc0 = fmaf(v.w, w0.w, acc0);
            acc1 = fmaf(v.x, w1.x, acc1); acc1 = fmaf(v.y, w1.y, acc1);
            acc1 = fmaf(v.z, w1.z, acc1); acc1 = fmaf(v.w, w1.w, acc1);
        }
    }
    out[oi0] = fmaxf(fmaf(acc0, g_sc4[lane],      g_sh4[lane]),      0.f);
    out[oi1] = fmaxf(fmaf(acc1, g_sc4[lane + 32], g_sh4[lane + 32]), 0.f);
}

// ---------------- launch ----------------
extern "C" void kernel_launch(void* const* d_in, const int* in_sizes, int n_in,
                              void* d_out, int out_size) {
    const float* vf    = (const float*)d_in[0];
    const int*   coors = (const int*)d_in[1];
    int nv = in_sizes[0] / 3;

    const float* w1 = (const float*)d_in[3];  const float* g1 = (const float*)d_in[4];
    const float* b1 = (const float*)d_in[5];  const float* m1 = (const float*)d_in[6];
    const float* v1 = (const float*)d_in[7];
    const float* w2 = (const float*)d_in[8];  const float* g2 = (const float*)d_in[9];
    const float* b2 = (const float*)d_in[10]; const float* m2 = (const float*)d_in[11];
    const float* v2 = (const float*)d_in[12];
    const float* w3 = (const float*)d_in[13]; const float* g3 = (const float*)d_in[14];
    const float* b3 = (const float*)d_in[15]; const float* m3 = (const float*)d_in[16];
    const float* v3 = (const float*)d_in[17];
    const float* w4 = (const float*)d_in[18]; const float* g4 = (const float*)d_in[19];
    const float* b4 = (const float*)d_in[20]; const float* m4 = (const float*)d_in[21];
    const float* v4 = (const float*)d_in[22];

    k_prep<<<(55296 + 255) / 256, 256>>>(w1, g1, b1, m1, v1,
                                         w2, g2, b2, m2, v2,
                                         w3, g3, b3, m3, v3,
                                         w4, g4, b4, m4, v4);
    k_zerobits<<<(NW0 / 4 + 255) / 256, 256>>>();
    k_scatA<<<(nv + 255) / 256, 256>>>(coors, nv);
    k_scatB<<<(nv + 255) / 256, 256>>>(vf, coors, nv);

    k_conv1<<<N1 / 128, 128>>>();                 // 21504 blocks
    k_conv2<<<(N2 * 32) / 256, 256>>>();          // 45056 blocks, warp/point
    k_conv3<<<(N3 * 32) / 256, 256>>>();          // 5120 blocks
    k_conv4<<<(N4 * 32) / 256, 256>>>((float*)d_out);  // 2048 blocks
}

// round 3
// speedup vs baseline: 1.9117x; 1.2407x over previous
#include <cuda_runtime.h>

// ---------------- compile-time shapes ----------------
static constexpr int B_ = 2;
static constexpr int D0 = 41, H0 = 512, W0 = 512;
static constexpr int D1 = 21, H1 = 256, W1 = 256;
static constexpr int D2 = 11, H2 = 128, W2 = 128;
static constexpr int D3 = 5,  H3 = 64,  W3 = 64;

static constexpr int N0 = B_ * D0 * H0 * W0;   // 21,495,808
static constexpr int N1 = B_ * D1 * H1 * W1;   // 2,752,512
static constexpr int N2 = B_ * D2 * H2 * W2;   // 360,448
static constexpr int N3 = B_ * D3 * H3 * W3;   // 40,960
static constexpr int N4 = B_ * 2 * H3 * W3;    // 16,384
static constexpr int NW0 = N0 / 32;

// ---------------- scratch ----------------
__device__ __align__(16) float4        g_dense0[N0];
__device__ __align__(16) unsigned      g_bits[NW0];
__device__ __align__(16) float         g_h1[(size_t)N1 * 16];
__device__ unsigned char               g_m1[N1];
__device__ __align__(16) float         g_h2[(size_t)N2 * 32];
__device__ unsigned char               g_m2[N2];
__device__ __align__(16) float         g_h3[(size_t)N3 * 64];
__device__ unsigned char               g_m3[N3];

// transposed weights + folded BN
__device__ __align__(16) float g_wt1[27 * 3 * 16];     // [tap][ci][co]
__device__ __align__(16) float g_wt2[27 * 4 * 32 * 4]; // [tap][g4][co32] float4-of-ci
__device__ __align__(16) float g_wt3[27 * 32 * 64];    // [tap][ci][co]
__device__ __align__(16) float g_wt4[3 * 16 * 64 * 4]; // [kd][g16][co64] float4-of-ci
__device__ float g_sc1[16], g_sh1[16];
__device__ float g_sc2[32], g_sh2[32];
__device__ float g_sc3[64], g_sh3[64];
__device__ float g_sc4[64], g_sh4[64];

// ---------------- prep ----------------
__global__ void k_prep(const float* __restrict__ w1, const float* __restrict__ g1,
                       const float* __restrict__ b1, const float* __restrict__ rm1,
                       const float* __restrict__ rv1,
                       const float* __restrict__ w2, const float* __restrict__ g2,
                       const float* __restrict__ b2, const float* __restrict__ rm2,
                       const float* __restrict__ rv2,
                       const float* __restrict__ w3, const float* __restrict__ g3,
                       const float* __restrict__ b3, const float* __restrict__ rm3,
                       const float* __restrict__ rv3,
                       const float* __restrict__ w4, const float* __restrict__ g4,
                       const float* __restrict__ b4, const float* __restrict__ rm4,
                       const float* __restrict__ rv4) {
    int i = blockIdx.x * blockDim.x + threadIdx.x;
    if (i < 1296) {
        int co = i & 15, ci = (i >> 4) % 3, tap = i / 48;
        g_wt1[i] = w1[(co * 3 + ci) * 27 + tap];
    }
    if (i < 13824) {
        int e = i & 3, co = (i >> 2) & 31, gg = (i >> 7) & 3, tap = i >> 9;
        g_wt2[i] = w2[(co * 16 + (4 * gg + e)) * 27 + tap];
    }
    if (i < 55296) {  // conv3 [tap][ci][co]
        int co = i & 63, ci = (i >> 6) & 31, tap = i >> 11;
        g_wt3[i] = w3[(co * 32 + ci) * 27 + tap];
    }
    if (i < 12288) {
        int e = i & 3, co = (i >> 2) & 63, gg = (i >> 8) & 15, kd = i >> 12;
        g_wt4[i] = w4[(co * 64 + (4 * gg + e)) * 3 + kd];
    }
    if (i < 16) { float s = g1[i] * rsqrtf(rv1[i] + 1e-3f); g_sc1[i] = s; g_sh1[i] = b1[i] - rm1[i] * s; }
    if (i < 32) { float s = g2[i] * rsqrtf(rv2[i] + 1e-3f); g_sc2[i] = s; g_sh2[i] = b2[i] - rm2[i] * s; }
    if (i < 64) {
        float s3 = g3[i] * rsqrtf(rv3[i] + 1e-3f); g_sc3[i] = s3; g_sh3[i] = b3[i] - rm3[i] * s3;
        float s4 = g4[i] * rsqrtf(rv4[i] + 1e-3f); g_sc4[i] = s4; g_sh4[i] = b4[i] - rm4[i] * s4;
    }
}

// ---------------- scatter ----------------
__global__ void k_zerobits() {
    int i = blockIdx.x * blockDim.x + threadIdx.x;
    if (i < NW0 / 4) reinterpret_cast<uint4*>(g_bits)[i] = make_uint4(0, 0, 0, 0);
}

__global__ void k_scatA(const int* __restrict__ c, int nv) {
    int i = blockIdx.x * blockDim.x + threadIdx.x;
    if (i >= nv) return;
    int b = c[4*i], z = c[4*i+1], y = c[4*i+2], x = c[4*i+3];
    size_t cell = (((size_t)b * D0 + z) * H0 + y) * W0 + x;
    g_dense0[cell] = make_float4(0.f, 0.f, 0.f, 0.f);
    atomicOr(&g_bits[cell >> 5], 1u << (cell & 31));
}

__global__ void k_scatB(const float* __restrict__ f, const int* __restrict__ c, int nv) {
    int i = blockIdx.x * blockDim.x + threadIdx.x;
    if (i >= nv) return;
    int b = c[4*i], z = c[4*i+1], y = c[4*i+2], x = c[4*i+3];
    size_t cell = (((size_t)b * D0 + z) * H0 + y) * W0 + x;
    float* p = reinterpret_cast<float*>(&g_dense0[cell]);
    atomicAdd(p + 0, f[3*i + 0]);
    atomicAdd(p + 1, f[3*i + 1]);
    atomicAdd(p + 2, f[3*i + 2]);
}

// ---------------- conv1: 3->16, bitmap-gated, thread per point ----------------
__global__ void __launch_bounds__(128) k_conv1() {
    int idx = blockIdx.x * blockDim.x + threadIdx.x;
    int lane = threadIdx.x & 31;
    int ow = idx & 255; int t = idx >> 8;
    int oh = t & 255; t >>= 8;
    int od = t % D1; int b = t / D1;
    int base = ow - lane;
    int wk = base >> 4;

    unsigned bits27 = 0;
#pragma unroll
    for (int kd = 0; kd < 3; kd++) {
        int id = 2 * od - 1 + kd;
        bool dok = (unsigned)id < (unsigned)D0;
#pragma unroll
        for (int kh = 0; kh < 3; kh++) {
            int ih = 2 * oh - 1 + kh;
            bool rok = dok && ((unsigned)ih < (unsigned)H0);
            unsigned A = 0, Bw = 0, Cw = 0;
            if (rok) {
                size_t rw = ((((size_t)b * D0 + id) * H0) + ih) * (W0 / 32);
                if (wk > 0) A = g_bits[rw + wk - 1];
                Bw = g_bits[rw + wk];
                if (wk < 15) Cw = g_bits[rw + wk + 1];
            }
#pragma unroll
            for (int kw = 0; kw < 3; kw++) {
                unsigned qq = 2 * lane + 31 + kw;
                unsigned word = (qq < 32) ? A : ((qq < 64) ? Bw : Cw);
                unsigned bit = (word >> (qq & 31)) & 1u;
                bits27 |= bit << ((kd * 3 + kh) * 3 + kw);
            }
        }
    }
    if (!bits27) { g_m1[idx] = 0; return; }

    float acc[16];
#pragma unroll
    for (int i = 0; i < 16; i++) acc[i] = 0.f;
    const float4* wt = reinterpret_cast<const float4*>(g_wt1);
    int base0 = ((b * D0 + (2 * od - 1)) * H0 + (2 * oh - 1)) * W0 + (2 * ow - 1);
#pragma unroll
    for (int tap = 0; tap < 27; tap++) {
        if (bits27 & (1u << tap)) {
            int kd = tap / 9, kh = (tap / 3) % 3, kw = tap % 3;
            size_t cell = (size_t)(base0 + kd * (H0 * W0) + kh * W0 + kw);
            float4 v = __ldg(&g_dense0[cell]);
            float vv[3] = {v.x, v.y, v.z};
#pragma unroll
            for (int ci = 0; ci < 3; ci++) {
#pragma unroll
                for (int j = 0; j < 4; j++) {
                    float4 ww = __ldg(wt + (tap * 3 + ci) * 4 + j);
                    acc[j*4+0] = fmaf(vv[ci], ww.x, acc[j*4+0]);
                    acc[j*4+1] = fmaf(vv[ci], ww.y, acc[j*4+1]);
                    acc[j*4+2] = fmaf(vv[ci], ww.z, acc[j*4+2]);
                    acc[j*4+3] = fmaf(vv[ci], ww.w, acc[j*4+3]);
                }
            }
        }
    }
    float* outp = &g_h1[(size_t)idx * 16];
#pragma unroll
    for (int j = 0; j < 4; j++) {
        float4 o;
        o.x = fmaxf(fmaf(acc[j*4+0], g_sc1[j*4+0], g_sh1[j*4+0]), 0.f);
        o.y = fmaxf(fmaf(acc[j*4+1], g_sc1[j*4+1], g_sh1[j*4+1]), 0.f);
        o.z = fmaxf(fmaf(acc[j*4+2], g_sc1[j*4+2], g_sh1[j*4+2]), 0.f);
        o.w = fmaxf(fmaf(acc[j*4+3], g_sc1[j*4+3], g_sh1[j*4+3]), 0.f);
        reinterpret_cast<float4*>(outp)[j] = o;
    }
    g_m1[idx] = 1;
}

// ---------------- conv2: 16->32, warp per point, unrolled taps; writes zeros when inactive ----------------
__global__ void __launch_bounds__(256) k_conv2() {
    int gw = (blockIdx.x * blockDim.x + threadIdx.x) >> 5;
    int lane = threadIdx.x & 31;
    int ow = gw & 127; int t = gw >> 7;
    int oh = t & 127; t >>= 7;
    int od = t % D2; int b = t / D2;

    unsigned on = 0;
    if (lane < 27) {
        int kd = lane / 9, kh = (lane / 3) % 3, kw = lane % 3;
        int id = 2*od - 1 + kd, ih = 2*oh - 1 + kh, iw = 2*ow - 1 + kw;
        if ((unsigned)id < (unsigned)D1 && (unsigned)ih < (unsigned)H1 && (unsigned)iw < (unsigned)W1) {
            size_t cin = (((size_t)b * D1 + id) * H1 + ih) * W1 + iw;
            on = g_m1[cin];
        }
    }
    unsigned bits = __ballot_sync(0xffffffffu, on != 0);
    if (!bits) {
        g_h2[(size_t)gw * 32 + lane] = 0.f;   // dense conv3 reads all of h2
        if (lane == 0) g_m2[gw] = 0;
        return;
    }

    float acc = 0.f;
    const float4* wtb = reinterpret_cast<const float4*>(g_wt2);
    int base0 = ((b * D1 + (2 * od - 1)) * H1 + (2 * oh - 1)) * W1 + (2 * ow - 1);
#pragma unroll
    for (int tap = 0; tap < 27; tap++) {
        if (bits & (1u << tap)) {
            int kd = tap / 9, kh = (tap / 3) % 3, kw = tap % 3;    // constants after unroll
            size_t cin = (size_t)(base0 + kd * (H1 * W1) + kh * W1 + kw);
            const float4* hin = reinterpret_cast<const float4*>(&g_h1[cin * 16]);
            const float4* wv = wtb + tap * 128 + lane;
#pragma unroll
            for (int gg = 0; gg < 4; gg++) {
                float4 v  = __ldg(hin + gg);
                float4 ww = __ldg(wv + gg * 32);
                acc = fmaf(v.x, ww.x, acc);
                acc = fmaf(v.y, ww.y, acc);
                acc = fmaf(v.z, ww.z, acc);
                acc = fmaf(v.w, ww.w, acc);
            }
        }
    }
    float o = fmaxf(fmaf(acc, g_sc2[lane], g_sh2[lane]), 0.f);
    g_h2[(size_t)gw * 32 + lane] = o;
    if (lane == 0) g_m2[gw] = 1;
}

// ---------------- m3: mask for layer 3 (any of 27 m2 neighbors) ----------------
__global__ void __launch_bounds__(256) k_m3() {
    int idx = blockIdx.x * blockDim.x + threadIdx.x;
    if (idx >= N3) return;
    int ow = idx & 63; int t = idx >> 6;
    int oh = t & 63; t >>= 6;
    int od = t % D3; int b = t / D3;
    unsigned char m = 0;
#pragma unroll
    for (int kd = 0; kd < 3; kd++) {
        int id = 2*od + kd;
#pragma unroll
        for (int kh = 0; kh < 3; kh++) {
            int ih = 2*oh - 1 + kh;
            if ((unsigned)ih >= (unsigned)H2) continue;
#pragma unroll
            for (int kw = 0; kw < 3; kw++) {
                int iw = 2*ow - 1 + kw;
                if ((unsigned)iw >= (unsigned)W2) continue;
                size_t cin = (((size_t)b * D2 + id) * H2 + ih) * W2 + iw;
                m |= g_m2[cin];
            }
        }
    }
    g_m3[idx] = m ? 1 : 0;
}

// ---------------- conv3: 32->64 DENSE tiled GEMM ----------------
// block = 256 threads, tile = 64 points (4 oh x 16 ow) x 64 co, K = 27 taps x 32 ci
__global__ void __launch_bounds__(256) k_conv3() {
    __shared__ __align__(16) float As[64 * 32];   // [p][ci]
    __shared__ __align__(16) float Ws[32 * 64];   // [ci][co]

    int bx = blockIdx.x;                 // 640 blocks
    int ow0 = (bx & 3) * 16;
    int oh0 = ((bx >> 2) & 15) * 4;
    int odb = bx >> 6;                   // 0..9
    int od = odb % D3, b = odb / D3;

    int tid = threadIdx.x;
    int cg = tid & 15;  int co4 = cg * 4;
    int pg = tid >> 4;  int p4 = pg * 4;

    float acc[16];
#pragma unroll
    for (int i = 0; i < 16; i++) acc[i] = 0.f;

    const float4* h2f4  = reinterpret_cast<const float4*>(g_h2);
    const float4* wt3f4 = reinterpret_cast<const float4*>(g_wt3);
    float4* Asf4 = reinterpret_cast<float4*>(As);
    float4* Wsf4 = reinterpret_cast<float4*>(Ws);

    int kd = 0, kh = 0, kw = 0;
    for (int tap = 0; tap < 27; tap++) {
        __syncthreads();
        // stage input tile: 64 points x 32 ci
#pragma unroll
        for (int it = 0; it < 2; it++) {
            int s = tid + it * 256;           // 0..511
            int p = s >> 3, f4 = s & 7;
            int di = p >> 4, dj = p & 15;
            int ih = 2 * (oh0 + di) - 1 + kh;
            int iw = 2 * (ow0 + dj) - 1 + kw;
            int id = 2 * od + kd;
            float4 v = make_float4(0.f, 0.f, 0.f, 0.f);
            if ((unsigned)ih < (unsigned)H2 && (unsigned)iw < (unsigned)W2) {
                size_t cin = (((size_t)b * D2 + id) * H2 + ih) * W2 + iw;
                v = __ldg(&h2f4[cin * 8 + f4]);
            }
            Asf4[s] = v;
        }
        // stage weights: 32 ci x 64 co
#pragma unroll
        for (int it = 0; it < 2; it++) {
            int s = tid + it * 256;
            Wsf4[s] = __ldg(&wt3f4[tap * 512 + s]);
        }
        __syncthreads();

#pragma unroll
        for (int ci = 0; ci < 32; ci++) {
            float4 w = *reinterpret_cast<const float4*>(&Ws[ci * 64 + co4]);
            float a0 = As[(p4 + 0) * 32 + ci];
            float a1 = As[(p4 + 1) * 32 + ci];
            float a2 = As[(p4 + 2) * 32 + ci];
            float a3 = As[(p4 + 3) * 32 + ci];
            acc[0]  = fmaf(a0, w.x, acc[0]);  acc[1]  = fmaf(a0, w.y, acc[1]);
            acc[2]  = fmaf(a0, w.z, acc[2]);  acc[3]  = fmaf(a0, w.w, acc[3]);
            acc[4]  = fmaf(a1, w.x, acc[4]);  acc[5]  = fmaf(a1, w.y, acc[5]);
            acc[6]  = fmaf(a1, w.z, acc[6]);  acc[7]  = fmaf(a1, w.w, acc[7]);
            acc[8]  = fmaf(a2, w.x, acc[8]);  acc[9]  = fmaf(a2, w.y, acc[9]);
            acc[10] = fmaf(a2, w.z, acc[10]); acc[11] = fmaf(a2, w.w, acc[11]);
            acc[12] = fmaf(a3, w.x, acc[12]); acc[13] = fmaf(a3, w.y, acc[13]);
            acc[14] = fmaf(a3, w.z, acc[14]); acc[15] = fmaf(a3, w.w, acc[15]);
        }
        if (++kw == 3) { kw = 0; if (++kh == 3) { kh = 0; ++kd; } }
    }

    // epilogue: bn + relu + mask, store
    float sc[4], sh[4];
#pragma unroll
    for (int j = 0; j < 4; j++) { sc[j] = g_sc3[co4 + j]; sh[j] = g_sh3[co4 + j]; }
#pragma unroll
    for (int e = 0; e < 4; e++) {
        int p = p4 + e;
        int di = p >> 4, dj = p & 15;
        int lin = ((b * D3 + od) * H3 + (oh0 + di)) * W3 + (ow0 + dj);
        float m = g_m3[lin] ? 1.f : 0.f;
        float4 o;
        o.x = fmaxf(fmaf(acc[e*4+0], sc[0], sh[0]), 0.f) * m;
        o.y = fmaxf(fmaf(acc[e*4+1], sc[1], sh[1]), 0.f) * m;
        o.z = fmaxf(fmaf(acc[e*4+2], sc[2], sh[2]), 0.f) * m;
        o.w = fmaxf(fmaf(acc[e*4+3], sc[3], sh[3]), 0.f) * m;
        *reinterpret_cast<float4*>(&g_h3[(size_t)lin * 64 + co4]) = o;
    }
}

// ---------------- conv4: 64->64, k(3,1,1) s(2,1,1); warp per point; writes d_out ----------------
__global__ void __launch_bounds__(256) k_conv4(float* __restrict__ out) {
    int gw = (blockIdx.x * blockDim.x + threadIdx.x) >> 5;
    int lane = threadIdx.x & 31;
    int ow = gw & 63; int t = gw >> 6;
    int oh = t & 63; t >>= 6;
    int od = t & 1; int b = t >> 1;

    unsigned on = 0;
    if (lane < 3) {
        int id = 2*od + lane;
        size_t cin = (((size_t)b * D3 + id) * H3 + oh) * W3 + ow;
        on = g_m3[cin];
    }
    unsigned bits = __ballot_sync(0xffffffffu, on != 0);

    size_t obase = (size_t)b * 128 * 4096 + (size_t)oh * 64 + ow;
    size_t oi0 = obase + (size_t)(lane * 2 + od) * 4096;
    size_t oi1 = obase + (size_t)((lane + 32) * 2 + od) * 4096;

    if (!bits) { out[oi0] = 0.f; out[oi1] = 0.f; return; }

    float acc0 = 0.f, acc1 = 0.f;
    const float4* wtb = reinterpret_cast<const float4*>(g_wt4);
#pragma unroll
    for (int kd = 0; kd < 3; kd++) {
        if (bits & (1u << kd)) {
            int id = 2*od + kd;
            size_t cin = (((size_t)b * D3 + id) * H3 + oh) * W3 + ow;
            const float4* hin = reinterpret_cast<const float4*>(&g_h3[cin * 64]);
            const float4* wv = wtb + kd * 1024 + lane;
#pragma unroll
            for (int gg = 0; gg < 16; gg++) {
                float4 v  = __ldg(hin + gg);
                float4 w0 = __ldg(wv + gg * 64);
                float4 w1 = __ldg(wv + gg * 64 + 32);
                acc0 = fmaf(v.x, w0.x, acc0); acc0 = fmaf(v.y, w0.y, acc0);
                acc0 = fmaf(v.z, w0.z, acc0); acc0 = fmaf(v.w, w0.w, acc0);
                acc1 = fmaf(v.x, w1.x, acc1); acc1 = fmaf(v.y, w1.y, acc1);
                acc1 = fmaf(v.z, w1.z, acc1); acc1 = fmaf(v.w, w1.w, acc1);
            }
        }
    }
    out[oi0] = fmaxf(fmaf(acc0, g_sc4[lane],      g_sh4[lane]),      0.f);
    out[oi1] = fmaxf(fmaf(acc1, g_sc4[lane + 32], g_sh4[lane + 32]), 0.f);
}

// ---------------- launch ----------------
extern "C" void kernel_launch(void* const* d_in, const int* in_sizes, int n_in,
                              void* d_out, int out_size) {
    const float* vf    = (const float*)d_in[0];
    const int*   coors = (const int*)d_in[1];
    int nv = in_sizes[0] / 3;

    const float* w1 = (const float*)d_in[3];  const float* g1 = (const float*)d_in[4];
    const float* b1 = (const float*)d_in[5];  const float* m1 = (const float*)d_in[6];
    const float* v1 = (const float*)d_in[7];
    const float* w2 = (const float*)d_in[8];  const float* g2 = (const float*)d_in[9];
    const float* b2 = (const float*)d_in[10]; const float* m2 = (const float*)d_in[11];
    const float* v2 = (const float*)d_in[12];
    const float* w3 = (const float*)d_in[13]; const float* g3 = (const float*)d_in[14];
    const float* b3 = (const float*)d_in[15]; const float* m3 = (const float*)d_in[16];
    const float* v3 = (const float*)d_in[17];
    const float* w4 = (const float*)d_in[18]; const float* g4 = (const float*)d_in[19];
    const float* b4 = (const float*)d_in[20]; const float* m4 = (const float*)d_in[21];
    const float* v4 = (const float*)d_in[22];

    k_prep<<<(55296 + 255) / 256, 256>>>(w1, g1, b1, m1, v1,
                                         w2, g2, b2, m2, v2,
                                         w3, g3, b3, m3, v3,
                                         w4, g4, b4, m4, v4);
    k_zerobits<<<(NW0 / 4 + 255) / 256, 256>>>();
    k_scatA<<<(nv + 255) / 256, 256>>>(coors, nv);
    k_scatB<<<(nv + 255) / 256, 256>>>(vf, coors, nv);

    k_conv1<<<N1 / 128, 128>>>();
    k_conv2<<<(N2 * 32) / 256, 256>>>();
    k_m3<<<(N3 + 255) / 256, 256>>>();
    k_conv3<<<640, 256>>>();
    k_conv4<<<(N4 * 32) / 256, 256>>>((float*)d_out);
}

// round 4
// speedup vs baseline: 1.9119x; 1.0001x over previous
#include <cuda_runtime.h>

// ---------------- compile-time shapes ----------------
static constexpr int B_ = 2;
static constexpr int D0 = 41, H0 = 512, W0 = 512;
static constexpr int D1 = 21, H1 = 256, W1 = 256;
static constexpr int D2 = 11, H2 = 128, W2 = 128;
static constexpr int D3 = 5,  H3 = 64,  W3 = 64;

static constexpr int N0 = B_ * D0 * H0 * W0;
static constexpr int N1 = B_ * D1 * H1 * W1;
static constexpr int N2 = B_ * D2 * H2 * W2;
static constexpr int N3 = B_ * D3 * H3 * W3;
static constexpr int N4 = B_ * 2 * H3 * W3;
static constexpr int NW0 = N0 / 32;

// ---------------- scratch ----------------
__device__ __align__(16) float4        g_dense0[N0];
__device__ __align__(16) unsigned      g_bits[NW0];
__device__ __align__(16) float         g_h1[(size_t)N1 * 16];
__device__ unsigned char               g_m1[N1];
__device__ __align__(16) float         g_h2[(size_t)N2 * 32];
__device__ unsigned char               g_m2[N2];
__device__ __align__(16) float         g_h3[(size_t)N3 * 64];
__device__ unsigned char               g_m3[N3];

__device__ __align__(16) float g_wt1[27 * 3 * 16];
__device__ __align__(16) float g_wt2[27 * 4 * 32 * 4];
__device__ __align__(16) float g_wt3[27 * 32 * 64];
__device__ __align__(16) float g_wt4[3 * 16 * 64 * 4];
__device__ float g_sc1[16], g_sh1[16];
__device__ float g_sc2[32], g_sh2[32];
__device__ float g_sc3[64], g_sh3[64];
__device__ float g_sc4[64], g_sh4[64];

// ---------------- prep ----------------
__global__ void k_prep(const float* __restrict__ w1, const float* __restrict__ g1,
                       const float* __restrict__ b1, const float* __restrict__ rm1,
                       const float* __restrict__ rv1,
                       const float* __restrict__ w2, const float* __restrict__ g2,
                       const float* __restrict__ b2, const float* __restrict__ rm2,
                       const float* __restrict__ rv2,
                       const float* __restrict__ w3, const float* __restrict__ g3,
                       const float* __restrict__ b3, const float* __restrict__ rm3,
                       const float* __restrict__ rv3,
                       const float* __restrict__ w4, const float* __restrict__ g4,
                       const float* __restrict__ b4, const float* __restrict__ rm4,
                       const float* __restrict__ rv4) {
    int i = blockIdx.x * blockDim.x + threadIdx.x;
    if (i < 1296) {
        int co = i & 15, ci = (i >> 4) % 3, tap = i / 48;
        g_wt1[i] = w1[(co * 3 + ci) * 27 + tap];
    }
    if (i < 13824) {
        int e = i & 3, co = (i >> 2) & 31, gg = (i >> 7) & 3, tap = i >> 9;
        g_wt2[i] = w2[(co * 16 + (4 * gg + e)) * 27 + tap];
    }
    if (i < 55296) {
        int co = i & 63, ci = (i >> 6) & 31, tap = i >> 11;
        g_wt3[i] = w3[(co * 32 + ci) * 27 + tap];
    }
    if (i < 12288) {
        int e = i & 3, co = (i >> 2) & 63, gg = (i >> 8) & 15, kd = i >> 12;
        g_wt4[i] = w4[(co * 64 + (4 * gg + e)) * 3 + kd];
    }
    if (i < 16) { float s = g1[i] * rsqrtf(rv1[i] + 1e-3f); g_sc1[i] = s; g_sh1[i] = b1[i] - rm1[i] * s; }
    if (i < 32) { float s = g2[i] * rsqrtf(rv2[i] + 1e-3f); g_sc2[i] = s; g_sh2[i] = b2[i] - rm2[i] * s; }
    if (i < 64) {
        float s3 = g3[i] * rsqrtf(rv3[i] + 1e-3f); g_sc3[i] = s3; g_sh3[i] = b3[i] - rm3[i] * s3;
        float s4 = g4[i] * rsqrtf(rv4[i] + 1e-3f); g_sc4[i] = s4; g_sh4[i] = b4[i] - rm4[i] * s4;
    }
}

// ---------------- scatter ----------------
__global__ void k_zerobits() {
    int i = blockIdx.x * blockDim.x + threadIdx.x;
    if (i < NW0 / 4) reinterpret_cast<uint4*>(g_bits)[i] = make_uint4(0, 0, 0, 0);
}

__global__ void k_scatA(const int* __restrict__ c, int nv) {
    int i = blockIdx.x * blockDim.x + threadIdx.x;
    if (i >= nv) return;
    int b = c[4*i], z = c[4*i+1], y = c[4*i+2], x = c[4*i+3];
    size_t cell = (((size_t)b * D0 + z) * H0 + y) * W0 + x;
    g_dense0[cell] = make_float4(0.f, 0.f, 0.f, 0.f);
    atomicOr(&g_bits[cell >> 5], 1u << (cell & 31));
}

__global__ void k_scatB(const float* __restrict__ f, const int* __restrict__ c, int nv) {
    int i = blockIdx.x * blockDim.x + threadIdx.x;
    if (i >= nv) return;
    int b = c[4*i], z = c[4*i+1], y = c[4*i+2], x = c[4*i+3];
    size_t cell = (((size_t)b * D0 + z) * H0 + y) * W0 + x;
    float* p = reinterpret_cast<float*>(&g_dense0[cell]);
    atomicAdd(p + 0, f[3*i + 0]);
    atomicAdd(p + 1, f[3*i + 1]);
    atomicAdd(p + 2, f[3*i + 2]);
}

// ---------------- conv1 ----------------
__global__ void __launch_bounds__(128) k_conv1() {
    int idx = blockIdx.x * blockDim.x + threadIdx.x;
    int lane = threadIdx.x & 31;
    int ow = idx & 255; int t = idx >> 8;
    int oh = t & 255; t >>= 8;
    int od = t % D1; int b = t / D1;
    int base = ow - lane;
    int wk = base >> 4;

    unsigned bits27 = 0;
#pragma unroll
    for (int kd = 0; kd < 3; kd++) {
        int id = 2 * od - 1 + kd;
        bool dok = (unsigned)id < (unsigned)D0;
#pragma unroll
        for (int kh = 0; kh < 3; kh++) {
            int ih = 2 * oh - 1 + kh;
            bool rok = dok && ((unsigned)ih < (unsigned)H0);
            unsigned A = 0, Bw = 0, Cw = 0;
            if (rok) {
                size_t rw = ((((size_t)b * D0 + id) * H0) + ih) * (W0 / 32);
                if (wk > 0) A = g_bits[rw + wk - 1];
                Bw = g_bits[rw + wk];
                if (wk < 15) Cw = g_bits[rw + wk + 1];
            }
#pragma unroll
            for (int kw = 0; kw < 3; kw++) {
                unsigned qq = 2 * lane + 31 + kw;
                unsigned word = (qq < 32) ? A : ((qq < 64) ? Bw : Cw);
                unsigned bit = (word >> (qq & 31)) & 1u;
                bits27 |= bit << ((kd * 3 + kh) * 3 + kw);
            }
        }
    }
    if (!bits27) { g_m1[idx] = 0; return; }

    float acc[16];
#pragma unroll
    for (int i = 0; i < 16; i++) acc[i] = 0.f;
    const float4* wt = reinterpret_cast<const float4*>(g_wt1);
    int base0 = ((b * D0 + (2 * od - 1)) * H0 + (2 * oh - 1)) * W0 + (2 * ow - 1);
#pragma unroll
    for (int tap = 0; tap < 27; tap++) {
        if (bits27 & (1u << tap)) {
            int kd = tap / 9, kh = (tap / 3) % 3, kw = tap % 3;
            size_t cell = (size_t)(base0 + kd * (H0 * W0) + kh * W0 + kw);
            float4 v = __ldg(&g_dense0[cell]);
            float vv[3] = {v.x, v.y, v.z};
#pragma unroll
            for (int ci = 0; ci < 3; ci++) {
#pragma unroll
                for (int j = 0; j < 4; j++) {
                    float4 ww = __ldg(wt + (tap * 3 + ci) * 4 + j);
                    acc[j*4+0] = fmaf(vv[ci], ww.x, acc[j*4+0]);
                    acc[j*4+1] = fmaf(vv[ci], ww.y, acc[j*4+1]);
                    acc[j*4+2] = fmaf(vv[ci], ww.z, acc[j*4+2]);
                    acc[j*4+3] = fmaf(vv[ci], ww.w, acc[j*4+3]);
                }
            }
        }
    }
    float* outp = &g_h1[(size_t)idx * 16];
#pragma unroll
    for (int j = 0; j < 4; j++) {
        float4 o;
        o.x = fmaxf(fmaf(acc[j*4+0], g_sc1[j*4+0], g_sh1[j*4+0]), 0.f);
        o.y = fmaxf(fmaf(acc[j*4+1], g_sc1[j*4+1], g_sh1[j*4+1]), 0.f);
        o.z = fmaxf(fmaf(acc[j*4+2], g_sc1[j*4+2], g_sh1[j*4+2]), 0.f);
        o.w = fmaxf(fmaf(acc[j*4+3], g_sc1[j*4+3], g_sh1[j*4+3]), 0.f);
        reinterpret_cast<float4*>(outp)[j] = o;
    }
    g_m1[idx] = 1;
}

// ---------------- conv2: 16->32, warp per 2 adjacent-ow points ----------------
__global__ void __launch_bounds__(256) k_conv2() {
    int gp = (blockIdx.x * blockDim.x + threadIdx.x) >> 5;
    int lane = threadIdx.x & 31;
    int owp = gp & 63; int t = gp >> 6;
    int oh = t & 127; t >>= 7;
    int od = t % D2; int b = t / D2;

    unsigned on0 = 0, on1 = 0;
    if (lane < 27) {
        int kd = lane / 9, kh = (lane / 3) % 3, kw = lane % 3;
        int id = 2*od - 1 + kd, ih = 2*oh - 1 + kh;
        int iw0 = 4*owp - 1 + kw, iw1 = iw0 + 2;
        if ((unsigned)id < (unsigned)D1 && (unsigned)ih < (unsigned)H1) {
            size_t row = (((size_t)b * D1 + id) * H1 + ih) * W1;
            if ((unsigned)iw0 < (unsigned)W1) on0 = g_m1[row + iw0];
            if ((unsigned)iw1 < (unsigned)W1) on1 = g_m1[row + iw1];
        }
    }
    unsigned bits0 = __ballot_sync(0xffffffffu, on0 != 0);
    unsigned bits1 = __ballot_sync(0xffffffffu, on1 != 0);
    unsigned U = bits0 | bits1;

    int lin0 = ((b * D2 + od) * H2 + oh) * W2 + 2 * owp;
    if (!U) {
        g_h2[(size_t)lin0 * 32 + lane] = 0.f;
        g_h2[(size_t)(lin0 + 1) * 32 + lane] = 0.f;
        if (lane == 0) { g_m2[lin0] = 0; g_m2[lin0 + 1] = 0; }
        return;
    }

    float acc0 = 0.f, acc1 = 0.f;
    const float4* wtb = reinterpret_cast<const float4*>(g_wt2);
    int base0 = ((b * D1 + (2 * od - 1)) * H1 + (2 * oh - 1)) * W1 + (4 * owp - 1);
#pragma unroll
    for (int tap = 0; tap < 27; tap++) {
        if (U & (1u << tap)) {
            int kd = tap / 9, kh = (tap / 3) % 3, kw = tap % 3;
            size_t cin0 = (size_t)(base0 + kd * (H1 * W1) + kh * W1 + kw);
            const float4* h0 = reinterpret_cast<const float4*>(&g_h1[cin0 * 16]);
            const float4* h1p = h0 + 8;
            const float4* wv = wtb + tap * 128 + lane;
            bool a0 = (bits0 >> tap) & 1u;
            bool a1 = (bits1 >> tap) & 1u;
#pragma unroll
            for (int gg = 0; gg < 4; gg++) {
                float4 ww = __ldg(wv + gg * 32);
                if (a0) {
                    float4 v = __ldg(h0 + gg);
                    acc0 = fmaf(v.x, ww.x, acc0); acc0 = fmaf(v.y, ww.y, acc0);
                    acc0 = fmaf(v.z, ww.z, acc0); acc0 = fmaf(v.w, ww.w, acc0);
                }
                if (a1) {
                    float4 v = __ldg(h1p + gg);
                    acc1 = fmaf(v.x, ww.x, acc1); acc1 = fmaf(v.y, ww.y, acc1);
                    acc1 = fmaf(v.z, ww.z, acc1); acc1 = fmaf(v.w, ww.w, acc1);
                }
            }
        }
    }
    float m0 = bits0 ? 1.f : 0.f;
    float m1v = bits1 ? 1.f : 0.f;
    g_h2[(size_t)lin0 * 32 + lane]       = fmaxf(fmaf(acc0, g_sc2[lane], g_sh2[lane]), 0.f) * m0;
    g_h2[(size_t)(lin0 + 1) * 32 + lane] = fmaxf(fmaf(acc1, g_sc2[lane], g_sh2[lane]), 0.f) * m1v;
    if (lane == 0) { g_m2[lin0] = bits0 ? 1 : 0; g_m2[lin0 + 1] = bits1 ? 1 : 0; }
}

// ---------------- m3 ----------------
__global__ void __launch_bounds__(256) k_m3() {
    int idx = blockIdx.x * blockDim.x + threadIdx.x;
    if (idx >= N3) return;
    int ow = idx & 63; int t = idx >> 6;
    int oh = t & 63; t >>= 6;
    int od = t % D3; int b = t / D3;
    unsigned char m = 0;
#pragma unroll
    for (int kd = 0; kd < 3; kd++) {
        int id = 2*od + kd;
#pragma unroll
        for (int kh = 0; kh < 3; kh++) {
            int ih = 2*oh - 1 + kh;
            if ((unsigned)ih >= (unsigned)H2) continue;
#pragma unroll
            for (int kw = 0; kw < 3; kw++) {
                int iw = 2*ow - 1 + kw;
                if ((unsigned)iw >= (unsigned)W2) continue;
                size_t cin = (((size_t)b * D2 + id) * H2 + ih) * W2 + iw;
                m |= g_m2[cin];
            }
        }
    }
    g_m3[idx] = m ? 1 : 0;
}

// ---------------- conv3: dense tiled GEMM, double-buffered ----------------
__global__ void __launch_bounds__(256) k_conv3() {
    __shared__ __align__(16) float4 As[2][512];
    __shared__ __align__(16) float4 Ws[2][512];

    int bx = blockIdx.x;
    int ow0 = (bx & 3) * 16;
    int oh0 = ((bx >> 2) & 15) * 4;
    int odb = bx >> 6;
    int od = odb % D3, b = odb / D3;

    int tid = threadIdx.x;
    int cg = tid & 15;  int co4 = cg * 4;
    int pg = tid >> 4;  int p4 = pg * 4;

    const float4* h2f4  = reinterpret_cast<const float4*>(g_h2);
    const float4* wt3f4 = reinterpret_cast<const float4*>(g_wt3);

    int pA0 = tid >> 3,         fA0 = tid & 7;
    int pA1 = (tid + 256) >> 3, fA1 = tid & 7;
    int diA0 = pA0 >> 4, djA0 = pA0 & 15;
    int diA1 = pA1 >> 4, djA1 = pA1 & 15;

    float4 ra0, ra1, rw0, rw1;
    auto fetch = [&](int kd, int kh, int kw, int tap) {
        int id = 2 * od + kd;
        size_t plane = (((size_t)b * D2 + id) * H2) * W2;
        {
            int ih = 2 * (oh0 + diA0) - 1 + kh, iw = 2 * (ow0 + djA0) - 1 + kw;
            ra0 = make_float4(0.f, 0.f, 0.f, 0.f);
            if ((unsigned)ih < (unsigned)H2 && (unsigned)iw < (unsigned)W2)
                ra0 = __ldg(&h2f4[(plane + (size_t)ih * W2 + iw) * 8 + fA0]);
        }
        {
            int ih = 2 * (oh0 + diA1) - 1 + kh, iw = 2 * (ow0 + djA1) - 1 + kw;
            ra1 = make_float4(0.f, 0.f, 0.f, 0.f);
            if ((unsigned)ih < (unsigned)H2 && (unsigned)iw < (unsigned)W2)
                ra1 = __ldg(&h2f4[(plane + (size_t)ih * W2 + iw) * 8 + fA1]);
        }
        rw0 = __ldg(&wt3f4[tap * 512 + tid]);
        rw1 = __ldg(&wt3f4[tap * 512 + tid + 256]);
    };

    fetch(0, 0, 0, 0);
    As[0][tid] = ra0; As[0][tid + 256] = ra1;
    Ws[0][tid] = rw0; Ws[0][tid + 256] = rw1;
    __syncthreads();

    float acc[16];
#pragma unroll
    for (int i = 0; i < 16; i++) acc[i] = 0.f;

    int kd = 0, kh = 0, kw = 0;
#pragma unroll 1
    for (int tap = 0; tap < 27; tap++) {
        int cur = tap & 1;
        int nkw = kw + 1, nkh = kh, nkd = kd;
        if (nkw == 3) { nkw = 0; nkh++; }
        if (nkh == 3) { nkh = 0; nkd++; }
        if (tap < 26) fetch(nkd, nkh, nkw, tap + 1);

        const float* Asf = reinterpret_cast<const float*>(As[cur]);
        const float* Wsf = reinterpret_cast<const float*>(Ws[cur]);
#pragma unroll
        for (int ci = 0; ci < 32; ci++) {
            float4 w = *reinterpret_cast<const float4*>(&Wsf[ci * 64 + co4]);
            float a0 = Asf[(p4 + 0) * 32 + ci];
            float a1 = Asf[(p4 + 1) * 32 + ci];
            float a2 = Asf[(p4 + 2) * 32 + ci];
            float a3 = Asf[(p4 + 3) * 32 + ci];
            acc[0]  = fmaf(a0, w.x, acc[0]);  acc[1]  = fmaf(a0, w.y, acc[1]);
            acc[2]  = fmaf(a0, w.z, acc[2]);  acc[3]  = fmaf(a0, w.w, acc[3]);
            acc[4]  = fmaf(a1, w.x, acc[4]);  acc[5]  = fmaf(a1, w.y, acc[5]);
            acc[6]  = fmaf(a1, w.z, acc[6]);  acc[7]  = fmaf(a1, w.w, acc[7]);
            acc[8]  = fmaf(a2, w.x, acc[8]);  acc[9]  = fmaf(a2, w.y, acc[9]);
            acc[10] = fmaf(a2, w.z, acc[10]); acc[11] = fmaf(a2, w.w, acc[11]);
            acc[12] = fmaf(a3, w.x, acc[12]); acc[13] = fmaf(a3, w.y, acc[13]);
            acc[14] = fmaf(a3, w.z, acc[14]); acc[15] = fmaf(a3, w.w, acc[15]);
        }
        if (tap < 26) {
            int nxt = cur ^ 1;
            As[nxt][tid] = ra0; As[nxt][tid + 256] = ra1;
            Ws[nxt][tid] = rw0; Ws[nxt][tid + 256] = rw1;
            __syncthreads();
        }
        kw = nkw; kh = nkh; kd = nkd;
    }

    float sc[4], sh[4];
#pragma unroll
    for (int j = 0; j < 4; j++) { sc[j] = g_sc3[co4 + j]; sh[j] = g_sh3[co4 + j]; }
#pragma unroll
    for (int e = 0; e < 4; e++) {
        int p = p4 + e;
        int di = p >> 4, dj = p & 15;
        int lin = ((b * D3 + od) * H3 + (oh0 + di)) * W3 + (ow0 + dj);
        float m = g_m3[lin] ? 1.f : 0.f;
        float4 o;
        o.x = fmaxf(fmaf(acc[e*4+0], sc[0], sh[0]), 0.f) * m;
        o.y = fmaxf(fmaf(acc[e*4+1], sc[1], sh[1]), 0.f) * m;
        o.z = fmaxf(fmaf(acc[e*4+2], sc[2], sh[2]), 0.f) * m;
        o.w = fmaxf(fmaf(acc[e*4+3], sc[3], sh[3]), 0.f) * m;
        *reinterpret_cast<float4*>(&g_h3[(size_t)lin * 64 + co4]) = o;
    }
}

// ---------------- conv4 ----------------
__global__ void __launch_bounds__(256) k_conv4(float* __restrict__ out) {
    int gw = (blockIdx.x * blockDim.x + threadIdx.x) >> 5;
    int lane = threadIdx.x & 31;
    int ow = gw & 63; int t = gw >> 6;
    int oh = t & 63; t >>= 6;
    int od = t & 1; int b = t >> 1;

    unsigned on = 0;
    if (lane < 3) {
        int id = 2*od + lane;
        size_t cin = (((size_t)b * D3 + id) * H3 + oh) * W3 + ow;
        on = g_m3[cin];
    }
    unsigned bits = __ballot_sync(0xffffffffu, on != 0);

    size_t obase = (size_t)b * 128 * 4096 + (size_t)oh * 64 + ow;
    size_t oi0 = obase + (size_t)(lane * 2 + od) * 4096;
    size_t oi1 = obase + (size_t)((lane + 32) * 2 + od) * 4096;

    if (!bits) { out[oi0] = 0.f; out[oi1] = 0.f; return; }

    float acc0 = 0.f, acc1 = 0.f;
    const float4* wtb = reinterpret_cast<const float4*>(g_wt4);
#pragma unroll
    for (int kd = 0; kd < 3; kd++) {
        if (bits & (1u << kd)) {
            int id = 2*od + kd;
            size_t cin = (((size_t)b * D3 + id) * H3 + oh) * W3 + ow;
            const float4* hin = reinterpret_cast<const float4*>(&g_h3[cin * 64]);
            const float4* wv = wtb + kd * 1024 + lane;
#pragma unroll
            for (int gg = 0; gg < 16; gg++) {
                float4 v  = __ldg(hin + gg);
                float4 w0 = __ldg(wv + gg * 64);
                float4 w1 = __ldg(wv + gg * 64 + 32);
                acc0 = fmaf(v.x, w0.x, acc0); acc0 = fmaf(v.y, w0.y, acc0);
                acc0 = fmaf(v.z, w0.z, acc0); acc0 = fmaf(v.w, w0.w, acc0);
                acc1 = fmaf(v.x, w1.x, acc1); acc1 = fmaf(v.y, w1.y, acc1);
                acc1 = fmaf(v.z, w1.z, acc1); acc1 = fmaf(v.w, w1.w, acc1);
            }
        }
    }
    out[oi0] = fmaxf(fmaf(acc0, g_sc4[lane],      g_sh4[lane]),      0.f);
    out[oi1] = fmaxf(fmaf(acc1, g_sc4[lane + 32], g_sh4[lane + 32]), 0.f);
}

// ---------------- launch ----------------
extern "C" void kernel_launch(void* const* d_in, const int* in_sizes, int n_in,
                              void* d_out, int out_size) {
    const float* vf    = (const float*)d_in[0];
    const int*   coors = (const int*)d_in[1];
    int nv = in_sizes[0] / 3;

    const float* w1 = (const float*)d_in[3];  const float* g1 = (const float*)d_in[4];
    const float* b1 = (const float*)d_in[5];  const float* m1 = (const float*)d_in[6];
    const float* v1 = (const float*)d_in[7];
    const float* w2 = (const float*)d_in[8];  const float* g2 = (const float*)d_in[9];
    const float* b2 = (const float*)d_in[10]; const float* m2 = (const float*)d_in[11];
    const float* v2 = (const float*)d_in[12];
    const float* w3 = (const float*)d_in[13]; const float* g3 = (const float*)d_in[14];
    const float* b3 = (const float*)d_in[15]; const float* m3 = (const float*)d_in[16];
    const float* v3 = (const float*)d_in[17];
    const float* w4 = (const float*)d_in[18]; const float* g4 = (const float*)d_in[19];
    const float* b4 = (const float*)d_in[20]; const float* m4 = (const float*)d_in[21];
    const float* v4 = (const float*)d_in[22];

    k_prep<<<(55296 + 255) / 256, 256>>>(w1, g1, b1, m1, v1,
                                         w2, g2, b2, m2, v2,
                                         w3, g3, b3, m3, v3,
                                         w4, g4, b4, m4, v4);
    k_zerobits<<<(NW0 / 4 + 255) / 256, 256>>>();
    k_scatA<<<(nv + 255) / 256, 256>>>(coors, nv);
    k_scatB<<<(nv + 255) / 256, 256>>>(vf, coors, nv);

    k_conv1<<<N1 / 128, 128>>>();
    k_conv2<<<(N2 / 2 * 32) / 256, 256>>>();
    k_m3<<<(N3 + 255) / 256, 256>>>();
    k_conv3<<<640, 256>>>();
    k_conv4<<<(N4 * 32) / 256, 256>>>((float*)d_out);
}